// round 9
// baseline (speedup 1.0000x reference)
#include <cuda_runtime.h>
#include <cuda_bf16.h>
#include <cuda_fp16.h>
#include <cstdint>
#include <math_constants.h>

#define NN 100000
#define EE 1600000
#define NBLK 98

// ---------------- scratch ---------------------------------------------------
__device__ float  g_h[(size_t)NN * 128];
__device__ float  g_q[(size_t)NN * 128];
__device__ __half g_k[(size_t)NN * 128];
__device__ __half g_v[(size_t)NN * 128];
__device__ int    g_csrcol[EE];
__device__ int    g_rowptr[NN + 1];
__device__ int    g_cnt[NN];
__device__ int    g_bsum[NBLK];
__device__ int    g_boff[NBLK];
__device__ __nv_bfloat16 g_wt_hi[4 * 128 * 128];  // W^T, [w][n][k]
__device__ __nv_bfloat16 g_wt_lo[4 * 128 * 128];

// ---------------- helpers ---------------------------------------------------
__device__ __forceinline__ uint32_t smem_u32(const void* p) {
    uint32_t a;
    asm("{ .reg .u64 t; cvta.to.shared.u64 t, %1; cvt.u32.u64 %0, t; }"
        : "=r"(a) : "l"(p));
    return a;
}
__device__ __forceinline__ void ldm_x4(uint32_t& r0, uint32_t& r1,
                                       uint32_t& r2, uint32_t& r3, uint32_t addr) {
    asm volatile("ldmatrix.sync.aligned.m8n8.x4.shared.b16 {%0,%1,%2,%3}, [%4];"
                 : "=r"(r0), "=r"(r1), "=r"(r2), "=r"(r3) : "r"(addr));
}
__device__ __forceinline__ void mma_bf16(float* c, const uint32_t* a,
                                         uint32_t b0, uint32_t b1) {
    asm volatile(
        "mma.sync.aligned.m16n8k16.row.col.f32.bf16.bf16.f32 "
        "{%0,%1,%2,%3}, {%4,%5,%6,%7}, {%8,%9}, {%0,%1,%2,%3};"
        : "+f"(c[0]), "+f"(c[1]), "+f"(c[2]), "+f"(c[3])
        : "r"(a[0]), "r"(a[1]), "r"(a[2]), "r"(a[3]), "r"(b0), "r"(b1));
}
__device__ __forceinline__ unsigned pack_bf2(float x, float y) {
    __nv_bfloat162 t = __floats2bfloat162_rn(x, y);
    return *reinterpret_cast<unsigned*>(&t);
}
__device__ __forceinline__ void cp16(uint32_t dst, const void* src) {
    asm volatile("cp.async.cg.shared.global [%0], [%1], 16;"
                 :: "r"(dst), "l"(src) : "memory");
}
#define CP_COMMIT() asm volatile("cp.async.commit_group;" ::: "memory")
#define CP_WAIT0()  asm volatile("cp.async.wait_group 0;" ::: "memory")

// ================= prep: zero cnt + transpose/convert weights ===============
__global__ void k_prep(const float* __restrict__ W0, const float* __restrict__ W1,
                       const float* __restrict__ W2, const float* __restrict__ W3) {
    if (blockIdx.x < 391) {
        int i = blockIdx.x * 256 + threadIdx.x;
        if (i < NN) g_cnt[i] = 0;
    } else {
        int j = (blockIdx.x - 391) * 256 + threadIdx.x;  // [0, 65536)
        int w = j >> 14, rem = j & 16383;
        int n = rem >> 7, kk = rem & 127;
        const float* Wp = (w == 0) ? W0 : (w == 1) ? W1 : (w == 2) ? W2 : W3;
        float val = Wp[kk * 128 + n];
        float hi = __bfloat162float(__float2bfloat16_rn(val));
        g_wt_hi[j] = __float2bfloat16_rn(val);
        g_wt_lo[j] = __float2bfloat16_rn(val - hi);
    }
}

// ================= CSR build ===============================================
__global__ void k_hist(const int* __restrict__ rows) {
    int e = blockIdx.x * blockDim.x + threadIdx.x;
    if (e < EE) atomicAdd(&g_cnt[rows[e]], 1);
}

__global__ void __launch_bounds__(256) k_scan_block() {
    __shared__ int ws[8];
    int b = blockIdx.x, t = threadIdx.x;
    int i0 = b * 1024 + t * 4;
    int v0 = 0, v1 = 0, v2 = 0, v3 = 0;
    if (i0 < NN) {
        if (i0 + 3 < NN) {
            int4 vv = *reinterpret_cast<const int4*>(&g_cnt[i0]);
            v0 = vv.x; v1 = vv.y; v2 = vv.z; v3 = vv.w;
            *reinterpret_cast<int4*>(&g_cnt[i0]) = make_int4(0, 0, 0, 0);
        } else {
            v0 = g_cnt[i0]; g_cnt[i0] = 0;
            if (i0 + 1 < NN) { v1 = g_cnt[i0 + 1]; g_cnt[i0 + 1] = 0; }
            if (i0 + 2 < NN) { v2 = g_cnt[i0 + 2]; g_cnt[i0 + 2] = 0; }
        }
    }
    int tsum = v0 + v1 + v2 + v3;
    int lane = t & 31, wid = t >> 5;
    int x = tsum;
#pragma unroll
    for (int m = 1; m < 32; m <<= 1) {
        int y = __shfl_up_sync(0xffffffffu, x, m);
        if (lane >= m) x += y;
    }
    if (lane == 31) ws[wid] = x;
    __syncthreads();
    if (t == 0) {
        int r = 0;
#pragma unroll
        for (int i = 0; i < 8; i++) { int tmp = ws[i]; ws[i] = r; r += tmp; }
        g_bsum[b] = r;
    }
    __syncthreads();
    int off = ws[wid] + (x - tsum);
    if (i0 < NN) {
        g_rowptr[i0] = off;
        if (i0 + 1 < NN) g_rowptr[i0 + 1] = off + v0;
        if (i0 + 2 < NN) g_rowptr[i0 + 2] = off + v0 + v1;
        if (i0 + 3 < NN) g_rowptr[i0 + 3] = off + v0 + v1 + v2;
    }
}

__global__ void k_scan_tops() {
    int lane = threadIdx.x;
    int carry = 0;
    for (int b = 0; b < NBLK; b += 32) {
        int i = b + lane;
        int v = (i < NBLK) ? g_bsum[i] : 0;
        int x = v;
#pragma unroll
        for (int m = 1; m < 32; m <<= 1) {
            int y = __shfl_up_sync(0xffffffffu, x, m);
            if (lane >= m) x += y;
        }
        if (i < NBLK) g_boff[i] = carry + x - v;
        carry += __shfl_sync(0xffffffffu, x, 31);
    }
}

__global__ void k_scatter(const int* __restrict__ rows, const int* __restrict__ cols) {
    int e = blockIdx.x * blockDim.x + threadIdx.x;
    if (e >= EE) return;
    int r = rows[e];
    int pos = g_rowptr[r] + g_boff[r >> 10] + atomicAdd(&g_cnt[r], 1);
    g_csrcol[pos] = cols[e];
}

// ================= split-bf16 HMMA GEMM, 64-row tile, 2 CTA/SM =============
#define ROWB 272
#define SM_AHI  0
#define SM_ALO  (SM_AHI + 64 * ROWB)
#define SM_BHI  (SM_ALO + 64 * ROWB)
#define SM_BLO  (SM_BHI + 128 * ROWB)
#define SM_TOT  (SM_BLO + 128 * ROWB)   // 104448

__device__ __forceinline__ void stage_B_async(uint32_t smb, int t, int widx) {
    const char* bh = reinterpret_cast<const char*>(&g_wt_hi[(size_t)widx * 16384]);
    const char* bl = reinterpret_cast<const char*>(&g_wt_lo[(size_t)widx * 16384]);
#pragma unroll
    for (int i = t; i < 2048; i += 256) {
        uint32_t o = (i >> 4) * ROWB + (i & 15) * 16;
        cp16(smb + SM_BHI + o, bh + i * 16);
        cp16(smb + SM_BLO + o, bl + i * 16);
    }
}

// hmask bit wi: output wi is __half (else float)
__global__ void __launch_bounds__(256, 2)
k_gemm_tc(const float* __restrict__ A, int M, int nW, int hmask,
          int wx0, const float* __restrict__ bias0, float s0, void* __restrict__ C0,
          int wx1, const float* __restrict__ bias1, float s1, void* __restrict__ C1,
          int wx2, const float* __restrict__ bias2, float s2, void* __restrict__ C2) {
    extern __shared__ char sm[];
    const uint32_t smb = smem_u32(sm);
    const int t = threadIdx.x;
    const int wid = t >> 5, lane = t & 31;
    const int mb = wid >> 2, nb = wid & 3;
    const int row0 = blockIdx.x * 64;

    stage_B_async(smb, t, wx0);
    CP_COMMIT();

#pragma unroll
    for (int i = t; i < 2048; i += 256) {
        int r = i >> 5, c4 = i & 31;
        float4 v = make_float4(0.f, 0.f, 0.f, 0.f);
        if (row0 + r < M)
            v = *reinterpret_cast<const float4*>(&A[(size_t)(row0 + r) * 128 + c4 * 4]);
        float h0 = __bfloat162float(__float2bfloat16_rn(v.x));
        float h1 = __bfloat162float(__float2bfloat16_rn(v.y));
        float h2 = __bfloat162float(__float2bfloat16_rn(v.z));
        float h3 = __bfloat162float(__float2bfloat16_rn(v.w));
        uint32_t o = r * ROWB + c4 * 8;
        *reinterpret_cast<uint2*>(sm + SM_AHI + o) =
            make_uint2(pack_bf2(v.x, v.y), pack_bf2(v.z, v.w));
        *reinterpret_cast<uint2*>(sm + SM_ALO + o) =
            make_uint2(pack_bf2(v.x - h0, v.y - h1), pack_bf2(v.z - h2, v.w - h3));
    }
    CP_WAIT0();
    __syncthreads();

    for (int wi = 0; wi < nW; wi++) {
        const float* bias = (wi == 0) ? bias0 : (wi == 1) ? bias1 : bias2;
        float scale       = (wi == 0) ? s0 : (wi == 1) ? s1 : s2;
        void* C           = (wi == 0) ? C0 : (wi == 1) ? C1 : C2;
        const bool ho     = (hmask >> wi) & 1;

        float acc[2][4][4];
#pragma unroll
        for (int i = 0; i < 2; i++)
#pragma unroll
            for (int j = 0; j < 4; j++)
#pragma unroll
                for (int q = 0; q < 4; q++) acc[i][j][q] = 0.f;

#pragma unroll
        for (int ks = 0; ks < 8; ks++) {
            const int k0 = ks * 16;
            uint32_t ah[2][4], al[2][4];
#pragma unroll
            for (int ms = 0; ms < 2; ms++) {
                int r = mb * 32 + ms * 16 + (lane & 7) + ((lane >> 3) & 1) * 8;
                uint32_t off = r * ROWB + (k0 + (lane >> 4) * 8) * 2;
                ldm_x4(ah[ms][0], ah[ms][1], ah[ms][2], ah[ms][3], smb + SM_AHI + off);
                ldm_x4(al[ms][0], al[ms][1], al[ms][2], al[ms][3], smb + SM_ALO + off);
            }
            uint32_t bh[4][2], bl[4][2];
#pragma unroll
            for (int ng = 0; ng < 2; ng++) {
                int r = nb * 32 + ng * 16 + (lane & 7) + ((lane >= 16) ? 8 : 0);
                uint32_t off = r * ROWB + (k0 + ((lane >> 3) & 1) * 8) * 2;
                uint32_t r0, r1, r2, r3;
                ldm_x4(r0, r1, r2, r3, smb + SM_BHI + off);
                bh[2 * ng][0] = r0; bh[2 * ng][1] = r1;
                bh[2 * ng + 1][0] = r2; bh[2 * ng + 1][1] = r3;
                ldm_x4(r0, r1, r2, r3, smb + SM_BLO + off);
                bl[2 * ng][0] = r0; bl[2 * ng][1] = r1;
                bl[2 * ng + 1][0] = r2; bl[2 * ng + 1][1] = r3;
            }
#pragma unroll
            for (int ms = 0; ms < 2; ms++)
#pragma unroll
                for (int nt = 0; nt < 4; nt++) {
                    mma_bf16(acc[ms][nt], ah[ms], bh[nt][0], bh[nt][1]);
                    mma_bf16(acc[ms][nt], ah[ms], bl[nt][0], bl[nt][1]);
                    mma_bf16(acc[ms][nt], al[ms], bh[nt][0], bh[nt][1]);
                }
        }

        __syncthreads();
        if (wi + 1 < nW) {
            stage_B_async(smb, t, (wi == 0) ? wx1 : wx2);
            CP_COMMIT();
        }

        const int g = lane >> 2, tq = lane & 3;
#pragma unroll
        for (int nt = 0; nt < 4; nt++) {
            int col = nb * 32 + nt * 8 + tq * 2;
            float b0 = __ldg(&bias[col]), b1 = __ldg(&bias[col + 1]);
#pragma unroll
            for (int ms = 0; ms < 2; ms++) {
                int r_lo = row0 + mb * 32 + ms * 16 + g;
#pragma unroll
                for (int hh = 0; hh < 2; hh++) {
                    int r = r_lo + hh * 8;
                    if (r >= M) continue;
                    float o0 = scale * (acc[ms][nt][2 * hh + 0] + b0);
                    float o1 = scale * (acc[ms][nt][2 * hh + 1] + b1);
                    if (ho) {
                        *reinterpret_cast<__half2*>(
                            &reinterpret_cast<__half*>(C)[(size_t)r * 128 + col]) =
                            __floats2half2_rn(o0, o1);
                    } else {
                        *reinterpret_cast<float2*>(
                            &reinterpret_cast<float*>(C)[(size_t)r * 128 + col]) =
                            make_float2(o0, o1);
                    }
                }
            }
        }
        if (wi + 1 < nW) {
            CP_WAIT0();
            __syncthreads();
        }
    }
}

// ================= fused per-row attention: single-pass online softmax =====
// warp per row; lane owns cols 4*lane..+3 (head = col%8, parity class lane&1).
// After the xor-shfl tree over masks 2..16, every lane holds the head-dots for
// its own parity class. Online update keeps (m, t, a) exact vs 2-pass.
__global__ void __launch_bounds__(256)
k_row(float* __restrict__ out) {
    int w = (blockIdx.x * blockDim.x + threadIdx.x) >> 5;
    if (w >= NN) return;
    const int lane = threadIdx.x & 31;
    const int s = g_rowptr[w] + g_boff[w >> 10];
    const int e = (w + 1 < NN) ? (g_rowptr[w + 1] + g_boff[(w + 1) >> 10]) : EE;

    float4 q = *reinterpret_cast<const float4*>(&g_q[(size_t)w * 128 + lane * 4]);

    float m0 = -CUDART_INF_F, m1 = -CUDART_INF_F, m2 = -CUDART_INF_F, m3 = -CUDART_INF_F;
    float t0 = 0.f, t1 = 0.f, t2 = 0.f, t3 = 0.f;
    float a0 = 0.f, a1 = 0.f, a2 = 0.f, a3 = 0.f;

    for (int i = s; i < e; i += 2) {
        int i1 = min(i + 1, e - 1);
        int c0 = __ldg(&g_csrcol[i]);
        int c1 = __ldg(&g_csrcol[i1]);
        uint2 kr0 = *reinterpret_cast<const uint2*>(&g_k[(size_t)c0 * 128 + lane * 4]);
        uint2 kr1 = *reinterpret_cast<const uint2*>(&g_k[(size_t)c1 * 128 + lane * 4]);
        uint2 vr0 = *reinterpret_cast<const uint2*>(&g_v[(size_t)c0 * 128 + lane * 4]);
        uint2 vr1 = *reinterpret_cast<const uint2*>(&g_v[(size_t)c1 * 128 + lane * 4]);
        float2 k0a = __half22float2(*reinterpret_cast<__half2*>(&kr0.x));
        float2 k0b = __half22float2(*reinterpret_cast<__half2*>(&kr0.y));
        float2 k1a = __half22float2(*reinterpret_cast<__half2*>(&kr1.x));
        float2 k1b = __half22float2(*reinterpret_cast<__half2*>(&kr1.y));

        float x0 = q.x * k0a.x, x1 = q.y * k0a.y, x2 = q.z * k0b.x, x3 = q.w * k0b.y;
        float y0 = q.x * k1a.x, y1 = q.y * k1a.y, y2 = q.z * k1b.x, y3 = q.w * k1b.y;
#pragma unroll
        for (int m = 2; m < 32; m <<= 1) {
            x0 += __shfl_xor_sync(0xffffffffu, x0, m);
            y0 += __shfl_xor_sync(0xffffffffu, y0, m);
            x1 += __shfl_xor_sync(0xffffffffu, x1, m);
            y1 += __shfl_xor_sync(0xffffffffu, y1, m);
            x2 += __shfl_xor_sync(0xffffffffu, x2, m);
            y2 += __shfl_xor_sync(0xffffffffu, y2, m);
            x3 += __shfl_xor_sync(0xffffffffu, x3, m);
            y3 += __shfl_xor_sync(0xffffffffu, y3, m);
        }

        float gg = (i + 1 < e) ? 1.f : 0.f;
        float n0 = fmaxf(m0, fmaxf(x0, y0));
        float n1 = fmaxf(m1, fmaxf(x1, y1));
        float n2 = fmaxf(m2, fmaxf(x2, y2));
        float n3 = fmaxf(m3, fmaxf(x3, y3));
        float sc0 = __expf(m0 - n0), sc1 = __expf(m1 - n1);
        float sc2 = __expf(m2 - n2), sc3 = __expf(m3 - n3);
        float e0 = __expf(x0 - n0), e1 = __expf(x1 - n1);
        float e2 = __expf(x2 - n2), e3 = __expf(x3 - n3);
        float f0 = gg * __expf(y0 - n0), f1 = gg * __expf(y1 - n1);
        float f2 = gg * __expf(y2 - n2), f3 = gg * __expf(y3 - n3);
        m0 = n0; m1 = n1; m2 = n2; m3 = n3;
        t0 = t0 * sc0 + e0 + f0;
        t1 = t1 * sc1 + e1 + f1;
        t2 = t2 * sc2 + e2 + f2;
        t3 = t3 * sc3 + e3 + f3;

        float2 v0a = __half22float2(*reinterpret_cast<__half2*>(&vr0.x));
        float2 v0b = __half22float2(*reinterpret_cast<__half2*>(&vr0.y));
        float2 v1a = __half22float2(*reinterpret_cast<__half2*>(&vr1.x));
        float2 v1b = __half22float2(*reinterpret_cast<__half2*>(&vr1.y));
        a0 = fmaf(a0, sc0, fmaf(e0, v0a.x, f0 * v1a.x));
        a1 = fmaf(a1, sc1, fmaf(e1, v0a.y, f1 * v1a.y));
        a2 = fmaf(a2, sc2, fmaf(e2, v0b.x, f2 * v1b.x));
        a3 = fmaf(a3, sc3, fmaf(e3, v0b.y, f3 * v1b.y));
    }

    float d0 = (t0 > 0.f) ? 1.0f / t0 : 0.f;
    float d1 = (t1 > 0.f) ? 1.0f / t1 : 0.f;
    float d2 = (t2 > 0.f) ? 1.0f / t2 : 0.f;
    float d3 = (t3 > 0.f) ? 1.0f / t3 : 0.f;
    *reinterpret_cast<float4*>(&out[(size_t)w * 128 + lane * 4]) =
        make_float4(a0 * d0, a1 * d1, a2 * d2, a3 * d3);
}

// ================= launch ===================================================
extern "C" void kernel_launch(void* const* d_in, const int* in_sizes, int n_in,
                              void* d_out, int out_size) {
    const float* X    = (const float*)d_in[0];
    const int*   rows = (const int*)d_in[1];
    const int*   cols = (const int*)d_in[2];
    const float* W_in = (const float*)d_in[3];
    const float* b_in = (const float*)d_in[4];
    const float* Wq   = (const float*)d_in[5];
    const float* bq   = (const float*)d_in[6];
    const float* Wk   = (const float*)d_in[7];
    const float* bk   = (const float*)d_in[8];
    const float* Wv   = (const float*)d_in[9];
    const float* bv   = (const float*)d_in[10];
    float* out = (float*)d_out;
    (void)in_sizes; (void)n_in; (void)out_size;

    cudaFuncSetAttribute(k_gemm_tc, cudaFuncAttributeMaxDynamicSharedMemorySize,
                         SM_TOT);

    void *ph, *pq, *pkk, *pv;
    cudaGetSymbolAddress(&ph, g_h);
    cudaGetSymbolAddress(&pq, g_q);
    cudaGetSymbolAddress(&pkk, g_k);
    cudaGetSymbolAddress(&pv, g_v);
    float* h = (float*)ph;

    const int gb = (NN + 63) / 64;

    k_prep<<<391 + 256, 256>>>(W_in, Wq, Wk, Wv);                 // 0
    k_hist<<<(EE + 255) / 256, 256>>>(rows);                       // 1
    k_scan_block<<<NBLK, 256>>>();                                 // 2
    k_gemm_tc<<<gb, 256, SM_TOT>>>(X, NN, 1, 0,                    // 3 (ncu)
                                   0, b_in, 1.0f, ph,
                                   0, nullptr, 0.f, nullptr,
                                   0, nullptr, 0.f, nullptr);
    k_gemm_tc<<<gb, 256, SM_TOT>>>(h, NN, 3, 0b110,                // 4: q fp32, k/v half
                                   1, bq, 0.25f, pq,
                                   2, bk, 1.0f, pkk,
                                   3, bv, 1.0f, pv);
    k_scan_tops<<<1, 32>>>();                                      // 5
    k_scatter<<<(EE + 255) / 256, 256>>>(rows, cols);              // 6
    k_row<<<(NN * 32 + 255) / 256, 256>>>(out);                    // 7
}

// round 10
// speedup vs baseline: 1.0018x; 1.0018x over previous
#include <cuda_runtime.h>
#include <cuda_bf16.h>
#include <cuda_fp16.h>
#include <cstdint>
#include <math_constants.h>

#define NN 100000
#define EE 1600000
#define NBLK 98

// ---------------- scratch ---------------------------------------------------
__device__ float  g_h[(size_t)NN * 128];
__device__ float  g_q[(size_t)NN * 128];
__device__ __half g_k[(size_t)NN * 128];
__device__ __half g_v[(size_t)NN * 128];
__device__ int    g_csrcol[EE];
__device__ int    g_rowptr[NN + 1];
__device__ int    g_cnt[NN];
__device__ int    g_bsum[NBLK];
__device__ int    g_boff[NBLK];
__device__ __nv_bfloat16 g_wt_hi[4 * 128 * 128];  // W^T, [w][n][k]
__device__ __nv_bfloat16 g_wt_lo[4 * 128 * 128];

// ---------------- helpers ---------------------------------------------------
__device__ __forceinline__ uint32_t smem_u32(const void* p) {
    uint32_t a;
    asm("{ .reg .u64 t; cvta.to.shared.u64 t, %1; cvt.u32.u64 %0, t; }"
        : "=r"(a) : "l"(p));
    return a;
}
__device__ __forceinline__ void ldm_x4(uint32_t& r0, uint32_t& r1,
                                       uint32_t& r2, uint32_t& r3, uint32_t addr) {
    asm volatile("ldmatrix.sync.aligned.m8n8.x4.shared.b16 {%0,%1,%2,%3}, [%4];"
                 : "=r"(r0), "=r"(r1), "=r"(r2), "=r"(r3) : "r"(addr));
}
__device__ __forceinline__ void mma_bf16(float* c, const uint32_t* a,
                                         uint32_t b0, uint32_t b1) {
    asm volatile(
        "mma.sync.aligned.m16n8k16.row.col.f32.bf16.bf16.f32 "
        "{%0,%1,%2,%3}, {%4,%5,%6,%7}, {%8,%9}, {%0,%1,%2,%3};"
        : "+f"(c[0]), "+f"(c[1]), "+f"(c[2]), "+f"(c[3])
        : "r"(a[0]), "r"(a[1]), "r"(a[2]), "r"(a[3]), "r"(b0), "r"(b1));
}
__device__ __forceinline__ unsigned pack_bf2(float x, float y) {
    __nv_bfloat162 t = __floats2bfloat162_rn(x, y);
    return *reinterpret_cast<unsigned*>(&t);
}
__device__ __forceinline__ void cp16(uint32_t dst, const void* src) {
    asm volatile("cp.async.cg.shared.global [%0], [%1], 16;"
                 :: "r"(dst), "l"(src) : "memory");
}
#define CP_COMMIT() asm volatile("cp.async.commit_group;" ::: "memory")
#define CP_WAIT0()  asm volatile("cp.async.wait_group 0;" ::: "memory")

// ================= prep: zero cnt + transpose/convert weights ===============
__global__ void k_prep(const float* __restrict__ W0, const float* __restrict__ W1,
                       const float* __restrict__ W2, const float* __restrict__ W3) {
    if (blockIdx.x < 391) {
        int i = blockIdx.x * 256 + threadIdx.x;
        if (i < NN) g_cnt[i] = 0;
    } else {
        int j = (blockIdx.x - 391) * 256 + threadIdx.x;  // [0, 65536)
        int w = j >> 14, rem = j & 16383;
        int n = rem >> 7, kk = rem & 127;
        const float* Wp = (w == 0) ? W0 : (w == 1) ? W1 : (w == 2) ? W2 : W3;
        float val = Wp[kk * 128 + n];
        float hi = __bfloat162float(__float2bfloat16_rn(val));
        g_wt_hi[j] = __float2bfloat16_rn(val);
        g_wt_lo[j] = __float2bfloat16_rn(val - hi);
    }
}

// ================= CSR build ===============================================
__global__ void k_hist(const int* __restrict__ rows) {
    int e = blockIdx.x * blockDim.x + threadIdx.x;
    if (e < EE) atomicAdd(&g_cnt[rows[e]], 1);
}

__global__ void __launch_bounds__(256) k_scan_block() {
    __shared__ int ws[8];
    int b = blockIdx.x, t = threadIdx.x;
    int i0 = b * 1024 + t * 4;
    int v0 = 0, v1 = 0, v2 = 0, v3 = 0;
    if (i0 < NN) {
        if (i0 + 3 < NN) {
            int4 vv = *reinterpret_cast<const int4*>(&g_cnt[i0]);
            v0 = vv.x; v1 = vv.y; v2 = vv.z; v3 = vv.w;
            *reinterpret_cast<int4*>(&g_cnt[i0]) = make_int4(0, 0, 0, 0);
        } else {
            v0 = g_cnt[i0]; g_cnt[i0] = 0;
            if (i0 + 1 < NN) { v1 = g_cnt[i0 + 1]; g_cnt[i0 + 1] = 0; }
            if (i0 + 2 < NN) { v2 = g_cnt[i0 + 2]; g_cnt[i0 + 2] = 0; }
        }
    }
    int tsum = v0 + v1 + v2 + v3;
    int lane = t & 31, wid = t >> 5;
    int x = tsum;
#pragma unroll
    for (int m = 1; m < 32; m <<= 1) {
        int y = __shfl_up_sync(0xffffffffu, x, m);
        if (lane >= m) x += y;
    }
    if (lane == 31) ws[wid] = x;
    __syncthreads();
    if (t == 0) {
        int r = 0;
#pragma unroll
        for (int i = 0; i < 8; i++) { int tmp = ws[i]; ws[i] = r; r += tmp; }
        g_bsum[b] = r;
    }
    __syncthreads();
    int off = ws[wid] + (x - tsum);
    if (i0 < NN) {
        g_rowptr[i0] = off;
        if (i0 + 1 < NN) g_rowptr[i0 + 1] = off + v0;
        if (i0 + 2 < NN) g_rowptr[i0 + 2] = off + v0 + v1;
        if (i0 + 3 < NN) g_rowptr[i0 + 3] = off + v0 + v1 + v2;
    }
}

__global__ void k_scan_tops() {
    int lane = threadIdx.x;
    int carry = 0;
    for (int b = 0; b < NBLK; b += 32) {
        int i = b + lane;
        int v = (i < NBLK) ? g_bsum[i] : 0;
        int x = v;
#pragma unroll
        for (int m = 1; m < 32; m <<= 1) {
            int y = __shfl_up_sync(0xffffffffu, x, m);
            if (lane >= m) x += y;
        }
        if (i < NBLK) g_boff[i] = carry + x - v;
        carry += __shfl_sync(0xffffffffu, x, 31);
    }
}

__global__ void k_scatter(const int* __restrict__ rows, const int* __restrict__ cols) {
    int e = blockIdx.x * blockDim.x + threadIdx.x;
    if (e >= EE) return;
    int r = rows[e];
    int pos = g_rowptr[r] + g_boff[r >> 10] + atomicAdd(&g_cnt[r], 1);
    g_csrcol[pos] = cols[e];
}

// ================= split-bf16 HMMA GEMM, 64-row tile, 2 CTA/SM =============
#define ROWB 272
#define SM_AHI  0
#define SM_ALO  (SM_AHI + 64 * ROWB)
#define SM_BHI  (SM_ALO + 64 * ROWB)
#define SM_BLO  (SM_BHI + 128 * ROWB)
#define SM_TOT  (SM_BLO + 128 * ROWB)   // 104448

__device__ __forceinline__ void stage_B_async(uint32_t smb, int t, int widx) {
    const char* bh = reinterpret_cast<const char*>(&g_wt_hi[(size_t)widx * 16384]);
    const char* bl = reinterpret_cast<const char*>(&g_wt_lo[(size_t)widx * 16384]);
#pragma unroll
    for (int i = t; i < 2048; i += 256) {
        uint32_t o = (i >> 4) * ROWB + (i & 15) * 16;
        cp16(smb + SM_BHI + o, bh + i * 16);
        cp16(smb + SM_BLO + o, bl + i * 16);
    }
}

// hmask bit wi: output wi is __half (else float)
__global__ void __launch_bounds__(256, 2)
k_gemm_tc(const float* __restrict__ A, int M, int nW, int hmask,
          int wx0, const float* __restrict__ bias0, float s0, void* __restrict__ C0,
          int wx1, const float* __restrict__ bias1, float s1, void* __restrict__ C1,
          int wx2, const float* __restrict__ bias2, float s2, void* __restrict__ C2) {
    extern __shared__ char sm[];
    const uint32_t smb = smem_u32(sm);
    const int t = threadIdx.x;
    const int wid = t >> 5, lane = t & 31;
    const int mb = wid >> 2, nb = wid & 3;
    const int row0 = blockIdx.x * 64;

    stage_B_async(smb, t, wx0);
    CP_COMMIT();

#pragma unroll
    for (int i = t; i < 2048; i += 256) {
        int r = i >> 5, c4 = i & 31;
        float4 v = make_float4(0.f, 0.f, 0.f, 0.f);
        if (row0 + r < M)
            v = *reinterpret_cast<const float4*>(&A[(size_t)(row0 + r) * 128 + c4 * 4]);
        float h0 = __bfloat162float(__float2bfloat16_rn(v.x));
        float h1 = __bfloat162float(__float2bfloat16_rn(v.y));
        float h2 = __bfloat162float(__float2bfloat16_rn(v.z));
        float h3 = __bfloat162float(__float2bfloat16_rn(v.w));
        uint32_t o = r * ROWB + c4 * 8;
        *reinterpret_cast<uint2*>(sm + SM_AHI + o) =
            make_uint2(pack_bf2(v.x, v.y), pack_bf2(v.z, v.w));
        *reinterpret_cast<uint2*>(sm + SM_ALO + o) =
            make_uint2(pack_bf2(v.x - h0, v.y - h1), pack_bf2(v.z - h2, v.w - h3));
    }
    CP_WAIT0();
    __syncthreads();

    for (int wi = 0; wi < nW; wi++) {
        const float* bias = (wi == 0) ? bias0 : (wi == 1) ? bias1 : bias2;
        float scale       = (wi == 0) ? s0 : (wi == 1) ? s1 : s2;
        void* C           = (wi == 0) ? C0 : (wi == 1) ? C1 : C2;
        const bool ho     = (hmask >> wi) & 1;

        float acc[2][4][4];
#pragma unroll
        for (int i = 0; i < 2; i++)
#pragma unroll
            for (int j = 0; j < 4; j++)
#pragma unroll
                for (int q = 0; q < 4; q++) acc[i][j][q] = 0.f;

#pragma unroll
        for (int ks = 0; ks < 8; ks++) {
            const int k0 = ks * 16;
            uint32_t ah[2][4], al[2][4];
#pragma unroll
            for (int ms = 0; ms < 2; ms++) {
                int r = mb * 32 + ms * 16 + (lane & 7) + ((lane >> 3) & 1) * 8;
                uint32_t off = r * ROWB + (k0 + (lane >> 4) * 8) * 2;
                ldm_x4(ah[ms][0], ah[ms][1], ah[ms][2], ah[ms][3], smb + SM_AHI + off);
                ldm_x4(al[ms][0], al[ms][1], al[ms][2], al[ms][3], smb + SM_ALO + off);
            }
            uint32_t bh[4][2], bl[4][2];
#pragma unroll
            for (int ng = 0; ng < 2; ng++) {
                int r = nb * 32 + ng * 16 + (lane & 7) + ((lane >= 16) ? 8 : 0);
                uint32_t off = r * ROWB + (k0 + ((lane >> 3) & 1) * 8) * 2;
                uint32_t r0, r1, r2, r3;
                ldm_x4(r0, r1, r2, r3, smb + SM_BHI + off);
                bh[2 * ng][0] = r0; bh[2 * ng][1] = r1;
                bh[2 * ng + 1][0] = r2; bh[2 * ng + 1][1] = r3;
                ldm_x4(r0, r1, r2, r3, smb + SM_BLO + off);
                bl[2 * ng][0] = r0; bl[2 * ng][1] = r1;
                bl[2 * ng + 1][0] = r2; bl[2 * ng + 1][1] = r3;
            }
#pragma unroll
            for (int ms = 0; ms < 2; ms++)
#pragma unroll
                for (int nt = 0; nt < 4; nt++) {
                    mma_bf16(acc[ms][nt], ah[ms], bh[nt][0], bh[nt][1]);
                    mma_bf16(acc[ms][nt], ah[ms], bl[nt][0], bl[nt][1]);
                    mma_bf16(acc[ms][nt], al[ms], bh[nt][0], bh[nt][1]);
                }
        }

        __syncthreads();
        if (wi + 1 < nW) {
            stage_B_async(smb, t, (wi == 0) ? wx1 : wx2);
            CP_COMMIT();
        }

        const int g = lane >> 2, tq = lane & 3;
#pragma unroll
        for (int nt = 0; nt < 4; nt++) {
            int col = nb * 32 + nt * 8 + tq * 2;
            float b0 = __ldg(&bias[col]), b1 = __ldg(&bias[col + 1]);
#pragma unroll
            for (int ms = 0; ms < 2; ms++) {
                int r_lo = row0 + mb * 32 + ms * 16 + g;
#pragma unroll
                for (int hh = 0; hh < 2; hh++) {
                    int r = r_lo + hh * 8;
                    if (r >= M) continue;
                    float o0 = scale * (acc[ms][nt][2 * hh + 0] + b0);
                    float o1 = scale * (acc[ms][nt][2 * hh + 1] + b1);
                    if (ho) {
                        *reinterpret_cast<__half2*>(
                            &reinterpret_cast<__half*>(C)[(size_t)r * 128 + col]) =
                            __floats2half2_rn(o0, o1);
                    } else {
                        *reinterpret_cast<float2*>(
                            &reinterpret_cast<float*>(C)[(size_t)r * 128 + col]) =
                            make_float2(o0, o1);
                    }
                }
            }
        }
        if (wi + 1 < nW) {
            CP_WAIT0();
            __syncthreads();
        }
    }
}

// ================= fused per-row attention: single-pass online softmax =====
// warp per row; lane owns cols 4*lane..+3 (head = col%8, parity class lane&1).
// After the xor-shfl tree over masks 2..16, every lane holds the head-dots for
// its own parity class. Online update keeps (m, t, a) exact vs 2-pass.
__global__ void __launch_bounds__(256)
k_row(float* __restrict__ out) {
    int w = (blockIdx.x * blockDim.x + threadIdx.x) >> 5;
    if (w >= NN) return;
    const int lane = threadIdx.x & 31;
    const int s = g_rowptr[w] + g_boff[w >> 10];
    const int e = (w + 1 < NN) ? (g_rowptr[w + 1] + g_boff[(w + 1) >> 10]) : EE;

    float4 q = *reinterpret_cast<const float4*>(&g_q[(size_t)w * 128 + lane * 4]);

    float m0 = -CUDART_INF_F, m1 = -CUDART_INF_F, m2 = -CUDART_INF_F, m3 = -CUDART_INF_F;
    float t0 = 0.f, t1 = 0.f, t2 = 0.f, t3 = 0.f;
    float a0 = 0.f, a1 = 0.f, a2 = 0.f, a3 = 0.f;

    for (int i = s; i < e; i += 2) {
        int i1 = min(i + 1, e - 1);
        int c0 = __ldg(&g_csrcol[i]);
        int c1 = __ldg(&g_csrcol[i1]);
        uint2 kr0 = *reinterpret_cast<const uint2*>(&g_k[(size_t)c0 * 128 + lane * 4]);
        uint2 kr1 = *reinterpret_cast<const uint2*>(&g_k[(size_t)c1 * 128 + lane * 4]);
        uint2 vr0 = *reinterpret_cast<const uint2*>(&g_v[(size_t)c0 * 128 + lane * 4]);
        uint2 vr1 = *reinterpret_cast<const uint2*>(&g_v[(size_t)c1 * 128 + lane * 4]);
        float2 k0a = __half22float2(*reinterpret_cast<__half2*>(&kr0.x));
        float2 k0b = __half22float2(*reinterpret_cast<__half2*>(&kr0.y));
        float2 k1a = __half22float2(*reinterpret_cast<__half2*>(&kr1.x));
        float2 k1b = __half22float2(*reinterpret_cast<__half2*>(&kr1.y));

        float x0 = q.x * k0a.x, x1 = q.y * k0a.y, x2 = q.z * k0b.x, x3 = q.w * k0b.y;
        float y0 = q.x * k1a.x, y1 = q.y * k1a.y, y2 = q.z * k1b.x, y3 = q.w * k1b.y;
#pragma unroll
        for (int m = 2; m < 32; m <<= 1) {
            x0 += __shfl_xor_sync(0xffffffffu, x0, m);
            y0 += __shfl_xor_sync(0xffffffffu, y0, m);
            x1 += __shfl_xor_sync(0xffffffffu, x1, m);
            y1 += __shfl_xor_sync(0xffffffffu, y1, m);
            x2 += __shfl_xor_sync(0xffffffffu, x2, m);
            y2 += __shfl_xor_sync(0xffffffffu, y2, m);
            x3 += __shfl_xor_sync(0xffffffffu, x3, m);
            y3 += __shfl_xor_sync(0xffffffffu, y3, m);
        }

        float gg = (i + 1 < e) ? 1.f : 0.f;
        float n0 = fmaxf(m0, fmaxf(x0, y0));
        float n1 = fmaxf(m1, fmaxf(x1, y1));
        float n2 = fmaxf(m2, fmaxf(x2, y2));
        float n3 = fmaxf(m3, fmaxf(x3, y3));
        float sc0 = __expf(m0 - n0), sc1 = __expf(m1 - n1);
        float sc2 = __expf(m2 - n2), sc3 = __expf(m3 - n3);
        float e0 = __expf(x0 - n0), e1 = __expf(x1 - n1);
        float e2 = __expf(x2 - n2), e3 = __expf(x3 - n3);
        float f0 = gg * __expf(y0 - n0), f1 = gg * __expf(y1 - n1);
        float f2 = gg * __expf(y2 - n2), f3 = gg * __expf(y3 - n3);
        m0 = n0; m1 = n1; m2 = n2; m3 = n3;
        t0 = t0 * sc0 + e0 + f0;
        t1 = t1 * sc1 + e1 + f1;
        t2 = t2 * sc2 + e2 + f2;
        t3 = t3 * sc3 + e3 + f3;

        float2 v0a = __half22float2(*reinterpret_cast<__half2*>(&vr0.x));
        float2 v0b = __half22float2(*reinterpret_cast<__half2*>(&vr0.y));
        float2 v1a = __half22float2(*reinterpret_cast<__half2*>(&vr1.x));
        float2 v1b = __half22float2(*reinterpret_cast<__half2*>(&vr1.y));
        a0 = fmaf(a0, sc0, fmaf(e0, v0a.x, f0 * v1a.x));
        a1 = fmaf(a1, sc1, fmaf(e1, v0a.y, f1 * v1a.y));
        a2 = fmaf(a2, sc2, fmaf(e2, v0b.x, f2 * v1b.x));
        a3 = fmaf(a3, sc3, fmaf(e3, v0b.y, f3 * v1b.y));
    }

    float d0 = (t0 > 0.f) ? 1.0f / t0 : 0.f;
    float d1 = (t1 > 0.f) ? 1.0f / t1 : 0.f;
    float d2 = (t2 > 0.f) ? 1.0f / t2 : 0.f;
    float d3 = (t3 > 0.f) ? 1.0f / t3 : 0.f;
    *reinterpret_cast<float4*>(&out[(size_t)w * 128 + lane * 4]) =
        make_float4(a0 * d0, a1 * d1, a2 * d2, a3 * d3);
}

// ================= launch ===================================================
extern "C" void kernel_launch(void* const* d_in, const int* in_sizes, int n_in,
                              void* d_out, int out_size) {
    const float* X    = (const float*)d_in[0];
    const int*   rows = (const int*)d_in[1];
    const int*   cols = (const int*)d_in[2];
    const float* W_in = (const float*)d_in[3];
    const float* b_in = (const float*)d_in[4];
    const float* Wq   = (const float*)d_in[5];
    const float* bq   = (const float*)d_in[6];
    const float* Wk   = (const float*)d_in[7];
    const float* bk   = (const float*)d_in[8];
    const float* Wv   = (const float*)d_in[9];
    const float* bv   = (const float*)d_in[10];
    float* out = (float*)d_out;
    (void)in_sizes; (void)n_in; (void)out_size;

    cudaFuncSetAttribute(k_gemm_tc, cudaFuncAttributeMaxDynamicSharedMemorySize,
                         SM_TOT);

    void *ph, *pq, *pkk, *pv;
    cudaGetSymbolAddress(&ph, g_h);
    cudaGetSymbolAddress(&pq, g_q);
    cudaGetSymbolAddress(&pkk, g_k);
    cudaGetSymbolAddress(&pv, g_v);
    float* h = (float*)ph;

    const int gb = (NN + 63) / 64;

    k_prep<<<391 + 256, 256>>>(W_in, Wq, Wk, Wv);                 // 0
    k_hist<<<(EE + 255) / 256, 256>>>(rows);                       // 1
    k_scan_block<<<NBLK, 256>>>();                                 // 2
    k_gemm_tc<<<gb, 256, SM_TOT>>>(X, NN, 1, 0,                    // 3 (ncu)
                                   0, b_in, 1.0f, ph,
                                   0, nullptr, 0.f, nullptr,
                                   0, nullptr, 0.f, nullptr);
    k_gemm_tc<<<gb, 256, SM_TOT>>>(h, NN, 3, 0b110,                // 4: q fp32, k/v half
                                   1, bq, 0.25f, pq,
                                   2, bk, 1.0f, pkk,
                                   3, bv, 1.0f, pv);
    k_scan_tops<<<1, 32>>>();                                      // 5
    k_scatter<<<(EE + 255) / 256, 256>>>(rows, cols);              // 6
    k_row<<<(NN * 32 + 255) / 256, 256>>>(out);                    // 7
}